// round 16
// baseline (speedup 1.0000x reference)
#include <cuda_runtime.h>
#include <stdint.h>

typedef unsigned long long u64;

// Fixed problem envelope: 2E = 1,600,000 (E=800,000), n = 50,000 (< 65536 so
// block-row/col ids fit 16 bits each of the 64-bit sort key).
#define E_MAX   850000
#define N_MAX   65536
#define ENT_MAX (N_MAX + 2*E_MAX)

__device__ float g_triu[(size_t)E_MAX * 16];   // LᵀR per first-half edge
__device__ float g_diag[(size_t)N_MAX * 16];   // per-node accumulated MᵀM
__device__ u64   g_entries[ENT_MAX];           // (r<<48)|(c<<32)|id
__device__ int   g_cnt[N_MAX];
__device__ int   g_fill[N_MAX];
__device__ int   g_rowstart[N_MAX + 1];

// one L2 atomic op per 16B row instead of four scalar REDs (sm_90+)
__device__ __forceinline__ void red4(float* p, float x, float y, float z, float w) {
    asm volatile("red.global.add.v4.f32 [%0], {%1,%2,%3,%4};"
                 :: "l"(__cvta_generic_to_global(p)),
                    "f"(x), "f"(y), "f"(z), "f"(w)
                 : "memory");
}

// ---------------------------------------------------------------- init
__global__ void k_init(int n) {
    int t = blockIdx.x * blockDim.x + threadIdx.x;
    if (t < n * 16) g_diag[t] = 0.0f;
    if (t < n) g_cnt[t] = 1;                  // +1 for the diag entry
}

// ---------------------------------------------------------------- counting
__global__ void __launch_bounds__(256) k_count(
    const int* __restrict__ ei, int E, int twoE) {
    int e = blockIdx.x * blockDim.x + threadIdx.x;
    if (e >= E) return;
    atomicAdd(&g_cnt[ei[e]], 1);              // row of edge e
    atomicAdd(&g_cnt[ei[twoE + e]], 1);       // col of edge e
}

// ------------------------------------------------- single-block tiled scan
// Coalesced tile loads + warp-shuffle scan (3 syncs/tile). Seeds each
// bucket's slot 0 with the diag entry and starts fill at 1.
__global__ void __launch_bounds__(1024) k_scan(int n, int total) {
    __shared__ int wsum[32];
    __shared__ int s_carry;
    int t = threadIdx.x, lane = t & 31, wid = t >> 5;
    if (t == 0) s_carry = 0;
    __syncthreads();
    for (int base = 0; base < n; base += 1024) {
        int i = base + t;
        int v = (i < n) ? g_cnt[i] : 0;
        int x = v;
#pragma unroll
        for (int off = 1; off < 32; off <<= 1) {
            int y = __shfl_up_sync(0xFFFFFFFFu, x, off);
            if (lane >= off) x += y;
        }
        if (lane == 31) wsum[wid] = x;
        __syncthreads();
        if (wid == 0) {
            int y = wsum[lane];
#pragma unroll
            for (int off = 1; off < 32; off <<= 1) {
                int z = __shfl_up_sync(0xFFFFFFFFu, y, off);
                if (lane >= off) y += z;
            }
            wsum[lane] = y;
        }
        __syncthreads();
        int incl = x + ((wid == 0) ? 0 : wsum[wid - 1]);
        int rs = s_carry + incl - v;
        if (i < n) {
            g_rowstart[i] = rs;
            g_fill[i] = 1;
            g_entries[rs] = ((u64)i << 48) | ((u64)i << 32) | (unsigned)i;  // id = i < n
        }
        __syncthreads();
        if (t == 1023) s_carry += incl;
        __syncthreads();
    }
    if (t == 0) g_rowstart[n] = total;
}

// ------------------------------------------------- per-edge 4x4 products
// diag accumulated with vector REDs: 8 × red.add.v4.f32 per edge (one L2
// atomic op per Gram row) instead of 32 scalar REDs. triu = LᵀR stored;
// ij/ji sort entries scattered (unordered — per-bucket sort restores exact
// stability via the monotone id).
__global__ void __launch_bounds__(256) k_edges(
    const float* __restrict__ maps, const int* __restrict__ ei,
    int E, int twoE, int n) {
    int e = blockIdx.x * blockDim.x + threadIdx.x;
    if (e >= E) return;

    float L[4][4], R[4][4];
    const float4* Lp = reinterpret_cast<const float4*>(maps) + e * 4;
    const float4* Rp = reinterpret_cast<const float4*>(maps) + (E + e) * 4;
#pragma unroll
    for (int a = 0; a < 4; a++) {
        float4 q = Lp[a];
        L[a][0] = q.x; L[a][1] = q.y; L[a][2] = q.z; L[a][3] = q.w;
        float4 p = Rp[a];
        R[a][0] = p.x; R[a][1] = p.y; R[a][2] = p.z; R[a][3] = p.w;
    }
    int nodeL = ei[e];          // == row for this edge
    int nodeR = ei[E + e];
    int col   = ei[twoE + e];

    // entry slots early to overlap atomic latency with the FMA work
    int q1 = g_rowstart[nodeL] + atomicAdd(&g_fill[nodeL], 1);
    int q2 = g_rowstart[col]   + atomicAdd(&g_fill[col], 1);

    float* dl = g_diag + (size_t)nodeL * 16;
    float* dr = g_diag + (size_t)nodeR * 16;
#pragma unroll
    for (int b = 0; b < 4; b++) {
        float s0 = L[0][b]*L[0][0] + L[1][b]*L[1][0] + L[2][b]*L[2][0] + L[3][b]*L[3][0];
        float s1 = L[0][b]*L[0][1] + L[1][b]*L[1][1] + L[2][b]*L[2][1] + L[3][b]*L[3][1];
        float s2 = L[0][b]*L[0][2] + L[1][b]*L[1][2] + L[2][b]*L[2][2] + L[3][b]*L[3][2];
        float s3 = L[0][b]*L[0][3] + L[1][b]*L[1][3] + L[2][b]*L[2][3] + L[3][b]*L[3][3];
        red4(dl + b * 4, s0, s1, s2, s3);
        float t0 = R[0][b]*R[0][0] + R[1][b]*R[1][0] + R[2][b]*R[2][0] + R[3][b]*R[3][0];
        float t1 = R[0][b]*R[0][1] + R[1][b]*R[1][1] + R[2][b]*R[2][1] + R[3][b]*R[3][1];
        float t2 = R[0][b]*R[0][2] + R[1][b]*R[1][2] + R[2][b]*R[2][2] + R[3][b]*R[3][2];
        float t3 = R[0][b]*R[0][3] + R[1][b]*R[1][3] + R[2][b]*R[2][3] + R[3][b]*R[3][3];
        red4(dr + b * 4, t0, t1, t2, t3);
    }

    float4* Tp = reinterpret_cast<float4*>(g_triu) + e * 4;
#pragma unroll
    for (int x = 0; x < 4; x++) {
        float4 t;
        t.x = L[0][x]*R[0][0] + L[1][x]*R[1][0] + L[2][x]*R[2][0] + L[3][x]*R[3][0];
        t.y = L[0][x]*R[0][1] + L[1][x]*R[1][1] + L[2][x]*R[2][1] + L[3][x]*R[3][1];
        t.z = L[0][x]*R[0][2] + L[1][x]*R[1][2] + L[2][x]*R[2][2] + L[3][x]*R[3][2];
        t.w = L[0][x]*R[0][3] + L[1][x]*R[1][3] + L[2][x]*R[2][3] + L[3][x]*R[3][3];
        Tp[x] = t;
    }

    g_entries[q1] = ((u64)nodeL << 48) | ((u64)col << 32) | (unsigned)(n + e);
    g_entries[q2] = ((u64)col << 48) | ((u64)nodeL << 32) | (unsigned)(n + E + e);
}

// ------------------------------------------------- value-block gather
__device__ __forceinline__ void load_block(
    unsigned id, int n, int E, float v[4][4]) {
    if (id < (unsigned)n) {
        const float4* dp = reinterpret_cast<const float4*>(g_diag) + (size_t)id * 4;
#pragma unroll
        for (int a = 0; a < 4; a++) {
            float4 q = dp[a];
            v[a][0] = q.x; v[a][1] = q.y; v[a][2] = q.z; v[a][3] = q.w;
        }
    } else if (id < (unsigned)(n + E)) {
        const float4* tp = reinterpret_cast<const float4*>(g_triu) + (size_t)(id - n) * 4;
#pragma unroll
        for (int a = 0; a < 4; a++) {
            float4 q = tp[a];
            v[a][0] = -q.x; v[a][1] = -q.y; v[a][2] = -q.z; v[a][3] = -q.w;
        }
    } else {
        const float4* tp = reinterpret_cast<const float4*>(g_triu) + (size_t)(id - n - E) * 4;
#pragma unroll
        for (int b = 0; b < 4; b++) {      // transposed: v[a][b] = -T[b][a]
            float4 q = tp[b];
            v[0][b] = -q.x; v[1][b] = -q.y; v[2][b] = -q.z; v[3][b] = -q.w;
        }
    }
}

// ------------------------------------------------- fused sort + emit
// One warp per block-row: keys sorted in shared (1KB/warp, 8KB/block — keeps
// full occupancy, unlike the R11 staged-output fusion), tie groups computed
// from shared, values gathered, stores issued directly (float4 fast path;
// consecutive sorted entries fill adjacent 16B halves of each 32B sector).
// g_entries is never written back — one read total.
__global__ void __launch_bounds__(256) k_sortwrite(
    float* __restrict__ out_i, float* __restrict__ out_j,
    float* __restrict__ out_v, int n, int E) {
    __shared__ u64 sb[8][128];
    int w = threadIdx.x >> 5, lane = threadIdx.x & 31;
    int r = blockIdx.x * 8 + w;
    if (r >= n) return;
    int rs = g_rowstart[r], re = g_rowstart[r + 1];
    int L = re - rs;
    u64* keys = sb[w];

    if (L <= 128) {
        int P = 2;
        while (P < L) P <<= 1;
        for (int i = lane; i < P; i += 32)
            keys[i] = (i < L) ? g_entries[rs + i] : ~0ULL;
        __syncwarp();
        for (int k = 2; k <= P; k <<= 1)
            for (int j = k >> 1; j > 0; j >>= 1) {
                for (int i = lane; i < P; i += 32) {
                    int x = i ^ j;
                    if (x > i) {
                        u64 A = keys[i], B = keys[x];
                        bool up = ((i & k) == 0);
                        if ((A > B) == up) { keys[i] = B; keys[x] = A; }
                    }
                }
                __syncwarp();
            }

        for (int k = lane; k < L; k += 32) {
            u64 key = keys[k];
            u64 hi  = key >> 32;
            int c   = (int)(hi & 0xFFFF);
            unsigned id = (unsigned)(key & 0xFFFFFFFFu);
            int gs = k;
            while (gs > 0 && (keys[gs - 1] >> 32) == hi) gs--;
            int ge = k + 1;
            while (ge < L && (keys[ge] >> 32) == hi) ge++;
            int eq = ge - gs, rk = k - gs;

            float v[4][4];
            load_block(id, n, E, v);

            int base = 16 * rs + 4 * gs;
            float fj0 = (float)(c * 4);
            if (eq == 1) {
#pragma unroll
                for (int a = 0; a < 4; a++) {
                    int pos = base + a * 4 * L;
                    float fi = (float)(r * 4 + a);
                    *reinterpret_cast<float4*>(out_i + pos) = make_float4(fi, fi, fi, fi);
                    *reinterpret_cast<float4*>(out_j + pos) =
                        make_float4(fj0, fj0 + 1.0f, fj0 + 2.0f, fj0 + 3.0f);
                    *reinterpret_cast<float4*>(out_v + pos) =
                        make_float4(v[a][0], v[a][1], v[a][2], v[a][3]);
                }
            } else {
#pragma unroll
                for (int a = 0; a < 4; a++)
#pragma unroll
                    for (int b = 0; b < 4; b++) {
                        int pos = base + a * 4 * L + b * eq + rk;
                        out_i[pos] = (float)(r * 4 + a);
                        out_j[pos] = fj0 + (float)b;
                        out_v[pos] = v[a][b];
                    }
            }
        }
    } else {
        // rare fallback: global odd-even sort, then emit from global
        for (int round = 0; round < L; round++) {
            for (int idx = rs + (round & 1) + 2 * lane; idx + 1 < re; idx += 64) {
                u64 A = g_entries[idx], B = g_entries[idx + 1];
                if (A > B) { g_entries[idx] = B; g_entries[idx + 1] = A; }
            }
            __syncwarp();
        }
        for (int k = lane; k < L; k += 32) {
            u64 key = g_entries[rs + k];
            u64 hi  = key >> 32;
            int c   = (int)(hi & 0xFFFF);
            unsigned id = (unsigned)(key & 0xFFFFFFFFu);
            int gs = k;
            while (gs > 0 && (g_entries[rs + gs - 1] >> 32) == hi) gs--;
            int ge = k + 1;
            while (ge < L && (g_entries[rs + ge] >> 32) == hi) ge++;
            int eq = ge - gs, rk = k - gs;

            float v[4][4];
            load_block(id, n, E, v);
            int base = 16 * rs + 4 * gs;
            float fj0 = (float)(c * 4);
#pragma unroll
            for (int a = 0; a < 4; a++)
#pragma unroll
                for (int b = 0; b < 4; b++) {
                    int pos = base + a * 4 * L + b * eq + rk;
                    out_i[pos] = (float)(r * 4 + a);
                    out_j[pos] = fj0 + (float)b;
                    out_v[pos] = v[a][b];
                }
        }
    }
}

// ---------------------------------------------------------------- launch
extern "C" void kernel_launch(void* const* d_in, const int* in_sizes, int n_in,
                              void* d_out, int out_size) {
    const float* maps = (const float*)d_in[0];
    const int*   ei   = (const int*)d_in[1];

    int twoE = in_sizes[0] / 16;        // 1,600,000
    int E    = twoE / 2;                // 800,000
    // out = [idx0 | idx1 | vals], each 16*(n+2E) fp32  =>  n = out/48 - 2E
    int n     = out_size / 48 - twoE;   // 50,000
    int total = n + twoE;               // block entries
    int nnz   = 16 * total;
    float* out = (float*)d_out;

    k_init <<<(n * 16 + 255) / 256, 256>>>(n);
    k_count<<<(E + 255) / 256, 256>>>(ei, E, twoE);
    k_scan <<<1, 1024>>>(n, total);
    k_edges<<<(E + 255) / 256, 256>>>(maps, ei, E, twoE, n);
    k_sortwrite<<<(n + 7) / 8, 256>>>(out, out + nnz, out + 2 * nnz, n, E);
}

// round 17
// speedup vs baseline: 1.2396x; 1.2396x over previous
#include <cuda_runtime.h>
#include <stdint.h>

typedef unsigned long long u64;

// Fixed problem envelope: 2E = 1,600,000 (E=800,000), n = 50,000 (< 65536 so
// block-row/col ids fit 16 bits each of the 64-bit sort key).
#define E_MAX   850000
#define N_MAX   65536
#define ENT_MAX (N_MAX + 2*E_MAX)

__device__ float g_triu[(size_t)E_MAX * 16];   // LᵀR per first-half edge
__device__ float g_diag[(size_t)N_MAX * 16];   // per-node accumulated MᵀM
__device__ u64   g_entries[ENT_MAX];           // (r<<48)|(c<<32)|id
__device__ int   g_cnt[N_MAX];
__device__ int   g_fill[N_MAX];
__device__ int   g_rowstart[N_MAX + 1];
__device__ int   g_part[512];

// one L2 atomic op per 16B row instead of four scalar REDs (sm_90+)
__device__ __forceinline__ void red4(float* p, float x, float y, float z, float w) {
    asm volatile("red.global.add.v4.f32 [%0], {%1,%2,%3,%4};"
                 :: "l"(__cvta_generic_to_global(p)),
                    "f"(x), "f"(y), "f"(z), "f"(w)
                 : "memory");
}

// ---------------------------------------------------------------- init
__global__ void k_init(int n, int total) {
    int t = blockIdx.x * blockDim.x + threadIdx.x;
    if (t < n * 16) g_diag[t] = 0.0f;
    if (t < n) g_cnt[t] = 1;                  // +1 for the diag entry
    if (t == 0) g_rowstart[n] = total;
}

// ---------------------------------------------------------------- counting
__global__ void __launch_bounds__(256) k_count(
    const int* __restrict__ ei, int E, int twoE) {
    int e = blockIdx.x * blockDim.x + threadIdx.x;
    if (e >= E) return;
    atomicAdd(&g_cnt[ei[e]], 1);              // row of edge e
    atomicAdd(&g_cnt[ei[twoE + e]], 1);       // col of edge e
}

// ------------------------------------------------- parallel 3-kernel scan
// (single-block merged scan was a hidden ~50-70us single-SM serialization)
__global__ void k_scan1(int m) {
    __shared__ int sh[256];
    int i = blockIdx.x * 256 + threadIdx.x;
    sh[threadIdx.x] = (i < m) ? g_cnt[i] : 0;
    __syncthreads();
#pragma unroll
    for (int s = 128; s > 0; s >>= 1) {
        if (threadIdx.x < s) sh[threadIdx.x] += sh[threadIdx.x + s];
        __syncthreads();
    }
    if (threadIdx.x == 0) g_part[blockIdx.x] = sh[0];
}

__global__ void k_scan2(int nblk) {   // 1 block, 512 threads, nblk <= 512
    __shared__ int sh[512];
    int v = (threadIdx.x < nblk) ? g_part[threadIdx.x] : 0;
    sh[threadIdx.x] = v;
    __syncthreads();
    for (int off = 1; off < 512; off <<= 1) {
        int t = (threadIdx.x >= off) ? sh[threadIdx.x - off] : 0;
        __syncthreads();
        sh[threadIdx.x] += t;
        __syncthreads();
    }
    if (threadIdx.x < nblk) g_part[threadIdx.x] = sh[threadIdx.x] - v;  // exclusive
}

// scan3 also seeds each bucket: slot 0 = diag entry, fill starts at 1.
__global__ void k_scan3(int m) {
    __shared__ int sh[256];
    int i = blockIdx.x * 256 + threadIdx.x;
    int v = (i < m) ? g_cnt[i] : 0;
    sh[threadIdx.x] = v;
    __syncthreads();
    for (int off = 1; off < 256; off <<= 1) {
        int t = (threadIdx.x >= off) ? sh[threadIdx.x - off] : 0;
        __syncthreads();
        sh[threadIdx.x] += t;
        __syncthreads();
    }
    if (i < m) {
        int rs = g_part[blockIdx.x] + sh[threadIdx.x] - v;
        g_rowstart[i] = rs;
        g_fill[i] = 1;
        g_entries[rs] = ((u64)i << 48) | ((u64)i << 32) | (unsigned)i;  // id = i < n
    }
}

// ------------------------------------------------- per-edge 4x4 products
// diag accumulated with vector REDs: 8 × red.add.v4.f32 per edge (one L2
// atomic op per Gram row) instead of 32 scalar REDs. triu = LᵀR stored;
// ij/ji sort entries scattered (unordered — per-bucket sort restores exact
// stability via the monotone id).
__global__ void __launch_bounds__(256) k_edges(
    const float* __restrict__ maps, const int* __restrict__ ei,
    int E, int twoE, int n) {
    int e = blockIdx.x * blockDim.x + threadIdx.x;
    if (e >= E) return;

    float L[4][4], R[4][4];
    const float4* Lp = reinterpret_cast<const float4*>(maps) + e * 4;
    const float4* Rp = reinterpret_cast<const float4*>(maps) + (E + e) * 4;
#pragma unroll
    for (int a = 0; a < 4; a++) {
        float4 q = Lp[a];
        L[a][0] = q.x; L[a][1] = q.y; L[a][2] = q.z; L[a][3] = q.w;
        float4 p = Rp[a];
        R[a][0] = p.x; R[a][1] = p.y; R[a][2] = p.z; R[a][3] = p.w;
    }
    int nodeL = ei[e];          // == row for this edge
    int nodeR = ei[E + e];
    int col   = ei[twoE + e];

    // entry slots early to overlap atomic latency with the FMA work
    int q1 = g_rowstart[nodeL] + atomicAdd(&g_fill[nodeL], 1);
    int q2 = g_rowstart[col]   + atomicAdd(&g_fill[col], 1);

    float* dl = g_diag + (size_t)nodeL * 16;
    float* dr = g_diag + (size_t)nodeR * 16;
#pragma unroll
    for (int b = 0; b < 4; b++) {
        float s0 = L[0][b]*L[0][0] + L[1][b]*L[1][0] + L[2][b]*L[2][0] + L[3][b]*L[3][0];
        float s1 = L[0][b]*L[0][1] + L[1][b]*L[1][1] + L[2][b]*L[2][1] + L[3][b]*L[3][1];
        float s2 = L[0][b]*L[0][2] + L[1][b]*L[1][2] + L[2][b]*L[2][2] + L[3][b]*L[3][2];
        float s3 = L[0][b]*L[0][3] + L[1][b]*L[1][3] + L[2][b]*L[2][3] + L[3][b]*L[3][3];
        red4(dl + b * 4, s0, s1, s2, s3);
        float t0 = R[0][b]*R[0][0] + R[1][b]*R[1][0] + R[2][b]*R[2][0] + R[3][b]*R[3][0];
        float t1 = R[0][b]*R[0][1] + R[1][b]*R[1][1] + R[2][b]*R[2][1] + R[3][b]*R[3][1];
        float t2 = R[0][b]*R[0][2] + R[1][b]*R[1][2] + R[2][b]*R[2][2] + R[3][b]*R[3][2];
        float t3 = R[0][b]*R[0][3] + R[1][b]*R[1][3] + R[2][b]*R[2][3] + R[3][b]*R[3][3];
        red4(dr + b * 4, t0, t1, t2, t3);
    }

    float4* Tp = reinterpret_cast<float4*>(g_triu) + e * 4;
#pragma unroll
    for (int x = 0; x < 4; x++) {
        float4 t;
        t.x = L[0][x]*R[0][0] + L[1][x]*R[1][0] + L[2][x]*R[2][0] + L[3][x]*R[3][0];
        t.y = L[0][x]*R[0][1] + L[1][x]*R[1][1] + L[2][x]*R[2][1] + L[3][x]*R[3][1];
        t.z = L[0][x]*R[0][2] + L[1][x]*R[1][2] + L[2][x]*R[2][2] + L[3][x]*R[3][2];
        t.w = L[0][x]*R[0][3] + L[1][x]*R[1][3] + L[2][x]*R[2][3] + L[3][x]*R[3][3];
        Tp[x] = t;
    }

    g_entries[q1] = ((u64)nodeL << 48) | ((u64)col << 32) | (unsigned)(n + e);
    g_entries[q2] = ((u64)col << 48) | ((u64)nodeL << 32) | (unsigned)(n + E + e);
}

// ------------------------------------------------- value-block gather
__device__ __forceinline__ void load_block(
    unsigned id, int n, int E, float v[4][4]) {
    if (id < (unsigned)n) {
        const float4* dp = reinterpret_cast<const float4*>(g_diag) + (size_t)id * 4;
#pragma unroll
        for (int a = 0; a < 4; a++) {
            float4 q = dp[a];
            v[a][0] = q.x; v[a][1] = q.y; v[a][2] = q.z; v[a][3] = q.w;
        }
    } else if (id < (unsigned)(n + E)) {
        const float4* tp = reinterpret_cast<const float4*>(g_triu) + (size_t)(id - n) * 4;
#pragma unroll
        for (int a = 0; a < 4; a++) {
            float4 q = tp[a];
            v[a][0] = -q.x; v[a][1] = -q.y; v[a][2] = -q.z; v[a][3] = -q.w;
        }
    } else {
        const float4* tp = reinterpret_cast<const float4*>(g_triu) + (size_t)(id - n - E) * 4;
#pragma unroll
        for (int b = 0; b < 4; b++) {      // transposed: v[a][b] = -T[b][a]
            float4 q = tp[b];
            v[0][b] = -q.x; v[1][b] = -q.y; v[2][b] = -q.z; v[3][b] = -q.w;
        }
    }
}

// ------------------------------------------------- fused sort + emit
// One warp per block-row: keys sorted in shared (1KB/warp — full occupancy),
// tie groups computed from shared, values gathered, stores issued directly
// (float4 fast path; a warp iteration's stores for fixed `a` cover ~512B
// contiguous). g_entries read exactly once, never written back.
__global__ void __launch_bounds__(256) k_sortwrite(
    float* __restrict__ out_i, float* __restrict__ out_j,
    float* __restrict__ out_v, int n, int E) {
    __shared__ u64 sb[8][128];
    int w = threadIdx.x >> 5, lane = threadIdx.x & 31;
    int r = blockIdx.x * 8 + w;
    if (r >= n) return;
    int rs = g_rowstart[r], re = g_rowstart[r + 1];
    int L = re - rs;
    u64* keys = sb[w];

    if (L <= 128) {
        int P = 2;
        while (P < L) P <<= 1;
        for (int i = lane; i < P; i += 32)
            keys[i] = (i < L) ? g_entries[rs + i] : ~0ULL;
        __syncwarp();
        for (int k = 2; k <= P; k <<= 1)
            for (int j = k >> 1; j > 0; j >>= 1) {
                for (int i = lane; i < P; i += 32) {
                    int x = i ^ j;
                    if (x > i) {
                        u64 A = keys[i], B = keys[x];
                        bool up = ((i & k) == 0);
                        if ((A > B) == up) { keys[i] = B; keys[x] = A; }
                    }
                }
                __syncwarp();
            }

        for (int k = lane; k < L; k += 32) {
            u64 key = keys[k];
            u64 hi  = key >> 32;
            int c   = (int)(hi & 0xFFFF);
            unsigned id = (unsigned)(key & 0xFFFFFFFFu);
            int gs = k;
            while (gs > 0 && (keys[gs - 1] >> 32) == hi) gs--;
            int ge = k + 1;
            while (ge < L && (keys[ge] >> 32) == hi) ge++;
            int eq = ge - gs, rk = k - gs;

            float v[4][4];
            load_block(id, n, E, v);

            int base = 16 * rs + 4 * gs;
            float fj0 = (float)(c * 4);
            if (eq == 1) {
#pragma unroll
                for (int a = 0; a < 4; a++) {
                    int pos = base + a * 4 * L;
                    float fi = (float)(r * 4 + a);
                    *reinterpret_cast<float4*>(out_i + pos) = make_float4(fi, fi, fi, fi);
                    *reinterpret_cast<float4*>(out_j + pos) =
                        make_float4(fj0, fj0 + 1.0f, fj0 + 2.0f, fj0 + 3.0f);
                    *reinterpret_cast<float4*>(out_v + pos) =
                        make_float4(v[a][0], v[a][1], v[a][2], v[a][3]);
                }
            } else {
#pragma unroll
                for (int a = 0; a < 4; a++)
#pragma unroll
                    for (int b = 0; b < 4; b++) {
                        int pos = base + a * 4 * L + b * eq + rk;
                        out_i[pos] = (float)(r * 4 + a);
                        out_j[pos] = fj0 + (float)b;
                        out_v[pos] = v[a][b];
                    }
            }
        }
    } else {
        // rare fallback: global odd-even sort, then emit from global
        for (int round = 0; round < L; round++) {
            for (int idx = rs + (round & 1) + 2 * lane; idx + 1 < re; idx += 64) {
                u64 A = g_entries[idx], B = g_entries[idx + 1];
                if (A > B) { g_entries[idx] = B; g_entries[idx + 1] = A; }
            }
            __syncwarp();
        }
        for (int k = lane; k < L; k += 32) {
            u64 key = g_entries[rs + k];
            u64 hi  = key >> 32;
            int c   = (int)(hi & 0xFFFF);
            unsigned id = (unsigned)(key & 0xFFFFFFFFu);
            int gs = k;
            while (gs > 0 && (g_entries[rs + gs - 1] >> 32) == hi) gs--;
            int ge = k + 1;
            while (ge < L && (g_entries[rs + ge] >> 32) == hi) ge++;
            int eq = ge - gs, rk = k - gs;

            float v[4][4];
            load_block(id, n, E, v);
            int base = 16 * rs + 4 * gs;
            float fj0 = (float)(c * 4);
#pragma unroll
            for (int a = 0; a < 4; a++)
#pragma unroll
                for (int b = 0; b < 4; b++) {
                    int pos = base + a * 4 * L + b * eq + rk;
                    out_i[pos] = (float)(r * 4 + a);
                    out_j[pos] = fj0 + (float)b;
                    out_v[pos] = v[a][b];
                }
        }
    }
}

// ---------------------------------------------------------------- launch
extern "C" void kernel_launch(void* const* d_in, const int* in_sizes, int n_in,
                              void* d_out, int out_size) {
    const float* maps = (const float*)d_in[0];
    const int*   ei   = (const int*)d_in[1];

    int twoE = in_sizes[0] / 16;        // 1,600,000
    int E    = twoE / 2;                // 800,000
    // out = [idx0 | idx1 | vals], each 16*(n+2E) fp32  =>  n = out/48 - 2E
    int n     = out_size / 48 - twoE;   // 50,000
    int total = n + twoE;               // block entries
    int nnz   = 16 * total;
    float* out = (float*)d_out;

    int nblk_scan = (n + 255) / 256;    // 196 <= 512

    k_init <<<(n * 16 + 255) / 256, 256>>>(n, total);
    k_count<<<(E + 255) / 256, 256>>>(ei, E, twoE);
    k_scan1<<<nblk_scan, 256>>>(n);
    k_scan2<<<1, 512>>>(nblk_scan);
    k_scan3<<<nblk_scan, 256>>>(n);
    k_edges<<<(E + 255) / 256, 256>>>(maps, ei, E, twoE, n);
    k_sortwrite<<<(n + 7) / 8, 256>>>(out, out + nnz, out + 2 * nnz, n, E);
}